// round 1
// baseline (speedup 1.0000x reference)
#include <cuda_runtime.h>

#define NIMG      32
#define IMH       512
#define IMW       512
#define PATCH     13
#define OWIDTH    500
#define OHEIGHT   500
#define SW        4          // output cols per thread
#define SH        25         // output rows per band
#define NBANDS    20         // 20 * 25 = 500 output rows
#define NSTRIPS   125        // 125 * 4 = 500 output cols
#define THREADS   128
#define EPSF      1e-5f

// per-(image,band) partials: [ccsum, S1, S2, S11, S22, S12]
__device__ float g_part[NIMG * NBANDS * 6];

__device__ __forceinline__ void load16(const float* __restrict__ p, float v[16]) {
    const float4* q = reinterpret_cast<const float4*>(p);
#pragma unroll
    for (int i = 0; i < 4; i++) {
        float4 t = __ldg(q + i);
        v[4*i+0] = t.x; v[4*i+1] = t.y; v[4*i+2] = t.z; v[4*i+3] = t.w;
    }
}

// Add (or subtract) the horizontal 13-tap sums of one input row into the
// per-thread 2D box accumulators for its SW output columns.
template<bool ADD>
__device__ __forceinline__ void accum_strip(float S0[SW], float S1[SW], float S2[SW],
                                            float S3[SW], float S4[SW],
                                            const float a[16], const float b[16]) {
    float h0 = 0.f, h1 = 0.f, h2 = 0.f, h3 = 0.f, h4 = 0.f;
#pragma unroll
    for (int k = 0; k < PATCH; k++) {
        float xa = a[k], xb = b[k];
        h0 += xa;
        h1 += xb;
        h2 = fmaf(xa, xa, h2);
        h3 = fmaf(xb, xb, h3);
        h4 = fmaf(xa, xb, h4);
    }
#pragma unroll
    for (int j = 0; j < SW; j++) {
        if (j > 0) {
            float xa = a[j + 12], xb = b[j + 12];
            float ya = a[j - 1],  yb = b[j - 1];
            h0 += xa - ya;
            h1 += xb - yb;
            h2 += fmaf(xa, xa, -(ya * ya));
            h3 += fmaf(xb, xb, -(yb * yb));
            h4 += fmaf(xa, xb, -(ya * yb));
        }
        if (ADD) { S0[j] += h0; S1[j] += h1; S2[j] += h2; S3[j] += h3; S4[j] += h4; }
        else     { S0[j] -= h0; S1[j] -= h1; S2[j] -= h2; S3[j] -= h3; S4[j] -= h4; }
    }
}

// Global-NCC partial sums over this thread's OWNED columns of one row.
__device__ __forceinline__ void accum_global(float gs[5], const float a[16],
                                             const float b[16], bool wide) {
    if (wide) {   // last strip owns all 16 loaded cols (496..511)
#pragma unroll
        for (int j = 0; j < 16; j++) {
            float xa = a[j], xb = b[j];
            gs[0] += xa; gs[1] += xb;
            gs[2] = fmaf(xa, xa, gs[2]);
            gs[3] = fmaf(xb, xb, gs[3]);
            gs[4] = fmaf(xa, xb, gs[4]);
        }
    } else {
#pragma unroll
        for (int j = 0; j < SW; j++) {
            float xa = a[j], xb = b[j];
            gs[0] += xa; gs[1] += xb;
            gs[2] = fmaf(xa, xa, gs[2]);
            gs[3] = fmaf(xb, xb, gs[3]);
            gs[4] = fmaf(xa, xb, gs[4]);
        }
    }
}

__global__ void __launch_bounds__(THREADS)
ncc_main_kernel(const float* __restrict__ x1, const float* __restrict__ x2) {
    const int band = blockIdx.x;
    const int img  = blockIdx.y;
    const int t    = threadIdx.x;
    const bool active    = (t < NSTRIPS);
    const bool last_band = (band == NBANDS - 1);
    const bool wide      = (t == NSTRIPS - 1);   // owns cols 496..511 for global sums

    const int c0 = t * SW;
    const int r0 = band * SH;

    const float* __restrict__ b1 = x1 + (size_t)img * IMH * IMW;
    const float* __restrict__ b2 = x2 + (size_t)img * IMH * IMW;

    float S0[SW], S1[SW], S2[SW], S3[SW], S4[SW];
#pragma unroll
    for (int j = 0; j < SW; j++) { S0[j]=0.f; S1[j]=0.f; S2[j]=0.f; S3[j]=0.f; S4[j]=0.f; }
    float gs[5] = {0.f, 0.f, 0.f, 0.f, 0.f};
    float ccacc = 0.f;

    if (active) {
        float a[16], bb[16];

        // ---- init: first 13 input rows of the band (all owned for global sums)
#pragma unroll 1
        for (int k = 0; k < PATCH; k++) {
            const int row = r0 + k;
            load16(b1 + (size_t)row * IMW + c0, a);
            load16(b2 + (size_t)row * IMW + c0, bb);
            accum_strip<true>(S0, S1, S2, S3, S4, a, bb);
            accum_global(gs, a, bb, wide);
        }

        const float INVN = 1.0f / 169.0f;

#pragma unroll 1
        for (int i = 0; i < SH; i++) {
            // ---- emit cc for output row r0 + i, cols c0 .. c0+3
#pragma unroll
            for (int j = 0; j < SW; j++) {
                float s1 = S0[j], s2 = S1[j], s11 = S2[j], s22 = S3[j], s12 = S4[j];
                float m1 = s1 * INVN;
                float m2 = s2 * INVN;
                float cross = fmaf(-s1, m2, s12);                 // s12 - s1*s2/n
                float v1 = fmaf(s11, INVN, -(m1 * m1)) + EPSF;    // biased var + eps
                float v2 = fmaf(s22, INVN, -(m2 * m2)) + EPSF;
                ccacc += cross * rsqrtf(v1 * v2);
            }

            if (i + 1 < SH) {
                // incoming input row
                const int rin = r0 + PATCH + i;
                load16(b1 + (size_t)rin * IMW + c0, a);
                load16(b2 + (size_t)rin * IMW + c0, bb);
                accum_strip<true>(S0, S1, S2, S3, S4, a, bb);
                // incoming row owned iff inside this band's owned rows,
                // or anywhere in the last band (which owns rows up to 511)
                if ((PATCH + i < SH) || last_band)
                    accum_global(gs, a, bb, wide);

                // departing input row (L1/L2 resident re-read; already counted)
                const int rout = r0 + i;
                load16(b1 + (size_t)rout * IMW + c0, a);
                load16(b2 + (size_t)rout * IMW + c0, bb);
                accum_strip<false>(S0, S1, S2, S3, S4, a, bb);
            }
        }
    }

    // ---- deterministic block reduction of (ccacc, gs[0..4])
    float vals[6] = {ccacc, gs[0], gs[1], gs[2], gs[3], gs[4]};
#pragma unroll
    for (int off = 16; off > 0; off >>= 1) {
#pragma unroll
        for (int q = 0; q < 6; q++)
            vals[q] += __shfl_down_sync(0xffffffffu, vals[q], off);
    }
    __shared__ float red[THREADS / 32][6];
    const int w = t >> 5, l = t & 31;
    if (l == 0) {
#pragma unroll
        for (int q = 0; q < 6; q++) red[w][q] = vals[q];
    }
    __syncthreads();
    if (t == 0) {
        float* dst = g_part + ((size_t)img * NBANDS + band) * 6;
#pragma unroll
        for (int q = 0; q < 6; q++)
            dst[q] = red[0][q] + red[1][q] + red[2][q] + red[3][q];
    }
}

__global__ void ncc_finalize_kernel(float* __restrict__ out) {
    const int b = threadIdx.x;
    if (b >= NIMG) return;
    float acc[6] = {0.f, 0.f, 0.f, 0.f, 0.f, 0.f};
    const float* src = g_part + (size_t)b * NBANDS * 6;
#pragma unroll 1
    for (int k = 0; k < NBANDS; k++) {
#pragma unroll
        for (int q = 0; q < 6; q++) acc[q] += src[k * 6 + q];
    }
    const float ccsum = acc[0];
    const float s1 = acc[1], s2 = acc[2], s11 = acc[3], s22 = acc[4], s12 = acc[5];
    const float Nf   = (float)(IMH * IMW);
    const float invN = 1.0f / Nf;
    const float m1 = s1 * invN;
    const float m2 = s2 * invN;
    const float v1 = fmaf(s11, invN, -(m1 * m1)) + EPSF;
    const float v2 = fmaf(s22, invN, -(m2 * m2)) + EPSF;
    const float g  = fmaf(s12, invN, -(m1 * m2)) * rsqrtf(v1 * v2);
    const float p  = ccsum * (1.0f / (500.0f * 500.0f * 169.0f));
    out[b] = 0.5f * g + 0.5f * p;
}

extern "C" void kernel_launch(void* const* d_in, const int* in_sizes, int n_in,
                              void* d_out, int out_size) {
    const float* x1 = (const float*)d_in[0];
    const float* x2 = (const float*)d_in[1];
    float* out = (float*)d_out;

    dim3 grid(NBANDS, NIMG);
    ncc_main_kernel<<<grid, THREADS>>>(x1, x2);
    ncc_finalize_kernel<<<1, 32>>>(out);
}

// round 2
// speedup vs baseline: 1.1070x; 1.1070x over previous
#include <cuda_runtime.h>

#define NIMG      32
#define IMH       512
#define IMW       512
#define PATCH     13
#define OWIDTH    500
#define SW        8          // output cols per thread
#define SH        25         // output rows per band
#define NBANDS    20         // 20 * 25 = 500 output rows
#define NSTRIPS   63         // ceil(500/8); last strip emits 4 cols
#define THREADS   64
#define NLOAD     20         // floats loaded per row per image (SW + 12)
#define EPSF      1e-5f

// per-(image,band) partials: [ccsum, S1, S2, S11, S22, S12]
__device__ float g_part[NIMG * NBANDS * 6];
__device__ unsigned int g_cnt[NIMG];   // zero-initialized; reset by finalizer

__device__ __forceinline__ void load_row(const float* __restrict__ p,
                                         float v[NLOAD], bool tail) {
    const float4* q = reinterpret_cast<const float4*>(p);
#pragma unroll
    for (int i = 0; i < 5; i++) {
        if (tail && i == 4) {
            v[16] = v[17] = v[18] = v[19] = 0.f;
        } else {
            float4 t = __ldg(q + i);
            v[4*i+0] = t.x; v[4*i+1] = t.y; v[4*i+2] = t.z; v[4*i+3] = t.w;
        }
    }
}

// Add (ADD=true) or subtract the horizontal 13-tap sums of one input row into
// the per-thread 2D box accumulators for its SW output columns.
template<bool ADD>
__device__ __forceinline__ void accum_strip(float S0[SW], float S1[SW], float S2[SW],
                                            float S3[SW], float S4[SW],
                                            const float a[NLOAD], const float b[NLOAD]) {
    float h0 = 0.f, h1 = 0.f, h2 = 0.f, h3 = 0.f, h4 = 0.f;
#pragma unroll
    for (int k = 0; k < PATCH; k++) {
        float xa = a[k], xb = b[k];
        h0 += xa;
        h1 += xb;
        h2 = fmaf(xa, xa, h2);
        h3 = fmaf(xb, xb, h3);
        h4 = fmaf(xa, xb, h4);
    }
#pragma unroll
    for (int j = 0; j < SW; j++) {
        if (j > 0) {
            float xa = a[j + 12], xb = b[j + 12];
            float ya = a[j - 1],  yb = b[j - 1];
            h0 += xa - ya;
            h1 += xb - yb;
            h2 += fmaf(xa, xa, -(ya * ya));
            h3 += fmaf(xb, xb, -(yb * yb));
            h4 += fmaf(xa, xb, -(ya * yb));
        }
        if (ADD) { S0[j] += h0; S1[j] += h1; S2[j] += h2; S3[j] += h3; S4[j] += h4; }
        else     { S0[j] -= h0; S1[j] -= h1; S2[j] -= h2; S3[j] -= h3; S4[j] -= h4; }
    }
}

// Global-NCC partial sums over this thread's OWNED columns of one row.
__device__ __forceinline__ void accum_global(float gs[5], const float a[NLOAD],
                                             const float b[NLOAD], bool wide) {
    const int lim = wide ? 16 : SW;   // last strip owns cols 496..511
#pragma unroll
    for (int j = 0; j < 16; j++) {
        if (j >= lim) break;
        float xa = a[j], xb = b[j];
        gs[0] += xa; gs[1] += xb;
        gs[2] = fmaf(xa, xa, gs[2]);
        gs[3] = fmaf(xb, xb, gs[3]);
        gs[4] = fmaf(xa, xb, gs[4]);
    }
}

__global__ void __launch_bounds__(THREADS)
ncc_fused_kernel(const float* __restrict__ x1, const float* __restrict__ x2,
                 float* __restrict__ out) {
    const int band = blockIdx.x;
    const int img  = blockIdx.y;
    const int t    = threadIdx.x;
    const bool active    = (t < NSTRIPS);
    const bool last_band = (band == NBANDS - 1);
    const bool wide      = (t == NSTRIPS - 1);
    const bool tail      = wide;                  // strip 62 must not load cols >= 512

    const int c0 = t * SW;
    const int r0 = band * SH;
    const int nvalid = active ? ((OWIDTH - c0) < SW ? (OWIDTH - c0) : SW) : 0;

    const float* __restrict__ b1 = x1 + (size_t)img * IMH * IMW;
    const float* __restrict__ b2 = x2 + (size_t)img * IMH * IMW;

    float S0[SW], S1[SW], S2[SW], S3[SW], S4[SW];
#pragma unroll
    for (int j = 0; j < SW; j++) { S0[j]=0.f; S1[j]=0.f; S2[j]=0.f; S3[j]=0.f; S4[j]=0.f; }
    float gs[5] = {0.f, 0.f, 0.f, 0.f, 0.f};
    float ccacc = 0.f;

    if (active) {
        float a[NLOAD], bb[NLOAD];

        // ---- init: first 13 input rows of the band (all owned for global sums)
#pragma unroll 1
        for (int k = 0; k < PATCH; k++) {
            const int row = r0 + k;
            load_row(b1 + (size_t)row * IMW + c0, a, tail);
            load_row(b2 + (size_t)row * IMW + c0, bb, tail);
            accum_strip<true>(S0, S1, S2, S3, S4, a, bb);
            accum_global(gs, a, bb, wide);
        }

        const float INVN = 1.0f / 169.0f;

#pragma unroll 1
        for (int i = 0; i < SH; i++) {
            const bool has_next = (i + 1 < SH);

            // prefetch incoming input row (L2 resident) before the emit math
            if (has_next) {
                const int rin = r0 + PATCH + i;
                load_row(b1 + (size_t)rin * IMW + c0, a, tail);
                load_row(b2 + (size_t)rin * IMW + c0, bb, tail);
            }

            // ---- emit cc for output row r0 + i, cols c0 .. c0+nvalid-1
#pragma unroll
            for (int j = 0; j < SW; j++) {
                if (j < nvalid) {
                    float s1 = S0[j], s2 = S1[j], s11 = S2[j], s22 = S3[j], s12 = S4[j];
                    float m1 = s1 * INVN;
                    float m2 = s2 * INVN;
                    float cross = fmaf(-s1, m2, s12);               // s12 - s1*s2/n
                    float v1 = fmaf(s11, INVN, -(m1 * m1)) + EPSF;  // biased var + eps
                    float v2 = fmaf(s22, INVN, -(m2 * m2)) + EPSF;
                    ccacc += cross * rsqrtf(v1 * v2);
                }
            }

            if (has_next) {
                accum_strip<true>(S0, S1, S2, S3, S4, a, bb);
                // incoming row owned iff inside band's owned rows, or last band
                if ((PATCH + i < SH) || last_band)
                    accum_global(gs, a, bb, wide);

                // departing input row (L1-resident re-read; already counted)
                const int rout = r0 + i;
                load_row(b1 + (size_t)rout * IMW + c0, a, tail);
                load_row(b2 + (size_t)rout * IMW + c0, bb, tail);
                accum_strip<false>(S0, S1, S2, S3, S4, a, bb);
            }
        }
    }

    // ---- deterministic block reduction of (ccacc, gs[0..4])
    float vals[6] = {ccacc, gs[0], gs[1], gs[2], gs[3], gs[4]};
#pragma unroll
    for (int off = 16; off > 0; off >>= 1) {
#pragma unroll
        for (int q = 0; q < 6; q++)
            vals[q] += __shfl_down_sync(0xffffffffu, vals[q], off);
    }
    __shared__ float red[THREADS / 32][6];
    __shared__ bool  is_last;
    const int w = t >> 5, l = t & 31;
    if (l == 0) {
#pragma unroll
        for (int q = 0; q < 6; q++) red[w][q] = vals[q];
    }
    __syncthreads();
    if (t == 0) {
        float* dst = g_part + ((size_t)img * NBANDS + band) * 6;
#pragma unroll
        for (int q = 0; q < 6; q++)
            dst[q] = red[0][q] + red[1][q];
        __threadfence();
        unsigned old = atomicAdd(&g_cnt[img], 1u);
        is_last = (old == NBANDS - 1);
    }
    __syncthreads();

    // ---- last block for this image finalizes (deterministic fixed-order sums)
    if (is_last) {
        __threadfence();
        __shared__ float comp[6];
        if (t < 6) {
            const float* src = g_part + (size_t)img * NBANDS * 6;
            float acc = 0.f;
#pragma unroll
            for (int k = 0; k < NBANDS; k++)
                acc += src[k * 6 + t];
            comp[t] = acc;
        }
        __syncthreads();
        if (t == 0) {
            const float ccsum = comp[0];
            const float s1 = comp[1], s2 = comp[2];
            const float s11 = comp[3], s22 = comp[4], s12 = comp[5];
            const float invN = 1.0f / (float)(IMH * IMW);
            const float m1 = s1 * invN;
            const float m2 = s2 * invN;
            const float v1 = fmaf(s11, invN, -(m1 * m1)) + EPSF;
            const float v2 = fmaf(s22, invN, -(m2 * m2)) + EPSF;
            const float g  = fmaf(s12, invN, -(m1 * m2)) * rsqrtf(v1 * v2);
            const float p  = ccsum * (1.0f / (500.0f * 500.0f * 169.0f));
            out[img] = 0.5f * g + 0.5f * p;
            g_cnt[img] = 0;   // reset for next launch / graph replay
        }
    }
}

extern "C" void kernel_launch(void* const* d_in, const int* in_sizes, int n_in,
                              void* d_out, int out_size) {
    const float* x1 = (const float*)d_in[0];
    const float* x2 = (const float*)d_in[1];
    float* out = (float*)d_out;

    dim3 grid(NBANDS, NIMG);
    ncc_fused_kernel<<<grid, THREADS>>>(x1, x2, out);
}